// round 1
// baseline (speedup 1.0000x reference)
#include <cuda_runtime.h>
#include <math.h>

// Problem constants
#define BATCH 2
#define TSEQ  1024
#define DIMM  512
#define NHEAD 8
#define DKH   64
#define NROWS (BATCH * TSEQ)   // 2048

// Scratch buffers (allocation-free rule: __device__ globals)
__device__ float g_Q[NROWS * DIMM];
__device__ float g_K[NROWS * DIMM];
__device__ float g_V[NROWS * DIMM];
__device__ float g_G[NROWS * DIMM];
__device__ float g_O[NROWS * DIMM];

// ---------------------------------------------------------------------------
// Kernel 1: fused projections  Q=relu(xWq), K=relu(xWk), V=xWv, G=sigmoid(xWg+bg)
// 64x64 tile, 256 threads, 4x4 microtile, BK=16
// ---------------------------------------------------------------------------
__global__ void __launch_bounds__(256) proj_kernel(
    const float* __restrict__ X,
    const float* __restrict__ Wq, const float* __restrict__ Wk,
    const float* __restrict__ Wv, const float* __restrict__ Wg,
    const float* __restrict__ bg)
{
    __shared__ float Xs[64][20];   // [m][k], pad to 20 (float4-aligned)
    __shared__ float Ws[16][64];   // [k][n]

    const int zi = blockIdx.z;
    const float* __restrict__ W = (zi == 0) ? Wq : (zi == 1) ? Wk : (zi == 2) ? Wv : Wg;
    float* __restrict__ Cout = (zi == 0) ? g_Q : (zi == 1) ? g_K : (zi == 2) ? g_V : g_G;

    const int tid = threadIdx.x;
    const int tx = tid & 15, ty = tid >> 4;
    const int m0 = blockIdx.y * 64, n0 = blockIdx.x * 64;

    const int lr = tid >> 2;            // 0..63 row for X load
    const int lk = (tid & 3) * 4;       // 0,4,8,12
    const int wr = tid >> 4;            // 0..15 k-row for W load
    const int wn = (tid & 15) * 4;      // 0..60

    float acc[4][4];
#pragma unroll
    for (int r = 0; r < 4; r++)
#pragma unroll
        for (int c = 0; c < 4; c++) acc[r][c] = 0.f;

    for (int k0 = 0; k0 < DIMM; k0 += 16) {
        float4 xv = *(const float4*)(X + (size_t)(m0 + lr) * DIMM + k0 + lk);
        float4 wv = *(const float4*)(W + (size_t)(k0 + wr) * DIMM + n0 + wn);
        __syncthreads();
        *(float4*)&Xs[lr][lk] = xv;
        *(float4*)&Ws[wr][wn] = wv;
        __syncthreads();
#pragma unroll
        for (int kk = 0; kk < 16; kk++) {
            float a0 = Xs[ty * 4 + 0][kk];
            float a1 = Xs[ty * 4 + 1][kk];
            float a2 = Xs[ty * 4 + 2][kk];
            float a3 = Xs[ty * 4 + 3][kk];
            float4 bv = *(float4*)&Ws[kk][tx * 4];
            acc[0][0] += a0 * bv.x; acc[0][1] += a0 * bv.y; acc[0][2] += a0 * bv.z; acc[0][3] += a0 * bv.w;
            acc[1][0] += a1 * bv.x; acc[1][1] += a1 * bv.y; acc[1][2] += a1 * bv.z; acc[1][3] += a1 * bv.w;
            acc[2][0] += a2 * bv.x; acc[2][1] += a2 * bv.y; acc[2][2] += a2 * bv.z; acc[2][3] += a2 * bv.w;
            acc[3][0] += a3 * bv.x; acc[3][1] += a3 * bv.y; acc[3][2] += a3 * bv.z; acc[3][3] += a3 * bv.w;
        }
    }

#pragma unroll
    for (int r = 0; r < 4; r++) {
        const int m = m0 + ty * 4 + r;
#pragma unroll
        for (int c = 0; c < 4; c++) {
            const int n = n0 + tx * 4 + c;
            float v = acc[r][c];
            if (zi <= 1) {
                v = fmaxf(v, 0.f);                        // relu for Q,K
            } else if (zi == 3) {
                v = 1.f / (1.f + expf(-(v + bg[n])));     // sigmoid gate
            }
            Cout[(size_t)m * DIMM + n] = v;
        }
    }
}

// ---------------------------------------------------------------------------
// Kernel 2: cosformer causal attention (quadratic tiled form)
// grid: (qtile=16, head=8, batch=2), 256 threads.
// S[t,s] = (Q_t . K_s) * (c_t c_s + s_t s_s), causal; O = S V / rowsum(S); *gate
// ---------------------------------------------------------------------------
#define ATTN_SMEM_FLOATS (3 * 64 * 65 + 64 * 64)
#define ATTN_SMEM_BYTES  (ATTN_SMEM_FLOATS * 4)

__global__ void __launch_bounds__(256) attn_kernel()
{
    extern __shared__ float sm[];
    float (*Qs)[65] = (float(*)[65])sm;                 // Q tile [tq][d]
    float (*Ks)[65] = (float(*)[65])(sm + 64 * 65);     // K tile [ts][d]
    float (*Ss)[65] = (float(*)[65])(sm + 2 * 64 * 65); // S tile [tq][ts]
    float (*Vs)[64] = (float(*)[64])(sm + 3 * 64 * 65); // V tile [ts][e]
    __shared__ float cq[64], sq[64], ck[64], sk[64];

    const int i = blockIdx.x;   // query tile
    const int h = blockIdx.y;
    const int b = blockIdx.z;
    const int tid = threadIdx.x;
    const int tx = tid & 15, ty = tid >> 4;

    const int lrow = tid >> 4;          // 0..15 (4 rows spaced by 16)
    const int lcol = (tid & 15) * 4;    // 0..60

    const float ANG = (float)(3.14159265358979323846 / 2048.0); // pi/(2T)

    // Load Q tile + query trig
    {
        const float* Qg = g_Q + ((size_t)(b * TSEQ + i * 64)) * DIMM + h * DKH;
#pragma unroll
        for (int rr = 0; rr < 4; rr++) {
            int row = lrow + rr * 16;
            float4 v = *(const float4*)(Qg + (size_t)row * DIMM + lcol);
            Qs[row][lcol + 0] = v.x; Qs[row][lcol + 1] = v.y;
            Qs[row][lcol + 2] = v.z; Qs[row][lcol + 3] = v.w;
        }
        if (tid < 64) {
            float s, c;
            sincosf((float)(i * 64 + tid) * ANG, &s, &c);
            cq[tid] = c; sq[tid] = s;
        }
    }

    float acc[4][4];
#pragma unroll
    for (int r = 0; r < 4; r++)
#pragma unroll
        for (int c = 0; c < 4; c++) acc[r][c] = 0.f;
    float zacc[4] = {0.f, 0.f, 0.f, 0.f};

    for (int j = 0; j <= i; j++) {
        __syncthreads();  // previous iteration done reading Ss/Vs; Q stores visible
        const float* Kg = g_K + ((size_t)(b * TSEQ + j * 64)) * DIMM + h * DKH;
        const float* Vg = g_V + ((size_t)(b * TSEQ + j * 64)) * DIMM + h * DKH;
#pragma unroll
        for (int rr = 0; rr < 4; rr++) {
            int row = lrow + rr * 16;
            float4 kv = *(const float4*)(Kg + (size_t)row * DIMM + lcol);
            Ks[row][lcol + 0] = kv.x; Ks[row][lcol + 1] = kv.y;
            Ks[row][lcol + 2] = kv.z; Ks[row][lcol + 3] = kv.w;
            float4 vv = *(const float4*)(Vg + (size_t)row * DIMM + lcol);
            *(float4*)&Vs[row][lcol] = vv;
        }
        if (tid < 64) {
            float s, c;
            sincosf((float)(j * 64 + tid) * ANG, &s, &c);
            ck[tid] = c; sk[tid] = s;
        }
        __syncthreads();

        // S = Q K^T (raw dot products)
        float sacc[4][4];
#pragma unroll
        for (int r = 0; r < 4; r++)
#pragma unroll
            for (int c = 0; c < 4; c++) sacc[r][c] = 0.f;
#pragma unroll 16
        for (int d = 0; d < 64; d++) {
            float a0 = Qs[ty * 4 + 0][d];
            float a1 = Qs[ty * 4 + 1][d];
            float a2 = Qs[ty * 4 + 2][d];
            float a3 = Qs[ty * 4 + 3][d];
            float b0 = Ks[tx * 4 + 0][d];
            float b1 = Ks[tx * 4 + 1][d];
            float b2 = Ks[tx * 4 + 2][d];
            float b3 = Ks[tx * 4 + 3][d];
            sacc[0][0] += a0 * b0; sacc[0][1] += a0 * b1; sacc[0][2] += a0 * b2; sacc[0][3] += a0 * b3;
            sacc[1][0] += a1 * b0; sacc[1][1] += a1 * b1; sacc[1][2] += a1 * b2; sacc[1][3] += a1 * b3;
            sacc[2][0] += a2 * b0; sacc[2][1] += a2 * b1; sacc[2][2] += a2 * b2; sacc[2][3] += a2 * b3;
            sacc[3][0] += a3 * b0; sacc[3][1] += a3 * b1; sacc[3][2] += a3 * b2; sacc[3][3] += a3 * b3;
        }

        // cos reweight + causal mask + z accumulation, stage S in smem
        const bool diag = (j == i);
#pragma unroll
        for (int r = 0; r < 4; r++) {
            const int tq = ty * 4 + r;
            const float cc = cq[tq], ss = sq[tq];
#pragma unroll
            for (int c = 0; c < 4; c++) {
                const int ts = tx * 4 + c;
                float w = cc * ck[ts] + ss * sk[ts];
                float sv = sacc[r][c] * w;
                if (diag && ts > tq) sv = 0.f;
                zacc[r] += sv;
                Ss[tq][ts] = sv;
            }
        }
        __syncthreads();

        // O += S @ V
#pragma unroll 8
        for (int ts = 0; ts < 64; ts++) {
            float a0 = Ss[ty * 4 + 0][ts];
            float a1 = Ss[ty * 4 + 1][ts];
            float a2 = Ss[ty * 4 + 2][ts];
            float a3 = Ss[ty * 4 + 3][ts];
            float4 bv = *(float4*)&Vs[ts][tx * 4];
            acc[0][0] += a0 * bv.x; acc[0][1] += a0 * bv.y; acc[0][2] += a0 * bv.z; acc[0][3] += a0 * bv.w;
            acc[1][0] += a1 * bv.x; acc[1][1] += a1 * bv.y; acc[1][2] += a1 * bv.z; acc[1][3] += a1 * bv.w;
            acc[2][0] += a2 * bv.x; acc[2][1] += a2 * bv.y; acc[2][2] += a2 * bv.z; acc[2][3] += a2 * bv.w;
            acc[3][0] += a3 * bv.x; acc[3][1] += a3 * bv.y; acc[3][2] += a3 * bv.z; acc[3][3] += a3 * bv.w;
        }
    }

    // reduce z over tx (lanes (ty&1)*16 + tx; xor bits 0..3 stay inside group)
    float zinv[4];
#pragma unroll
    for (int r = 0; r < 4; r++) {
        float z = zacc[r];
        z += __shfl_xor_sync(0xffffffffu, z, 1);
        z += __shfl_xor_sync(0xffffffffu, z, 2);
        z += __shfl_xor_sync(0xffffffffu, z, 4);
        z += __shfl_xor_sync(0xffffffffu, z, 8);
        zinv[r] = 1.f / fmaxf(z, 1e-6f);
    }

    // epilogue: normalize, gate, store
    float* Og = g_O + ((size_t)(b * TSEQ + i * 64)) * DIMM + h * DKH;
    const float* Gg = g_G + ((size_t)(b * TSEQ + i * 64)) * DIMM + h * DKH;
#pragma unroll
    for (int r = 0; r < 4; r++) {
#pragma unroll
        for (int c = 0; c < 4; c++) {
            const int off = (ty * 4 + r) * DIMM + tx * 4 + c;
            Og[off] = acc[r][c] * zinv[r] * Gg[off];
        }
    }
}

// ---------------------------------------------------------------------------
// Kernel 3: output GEMM  out = g_O @ Wo   (2048x512 @ 512x512)
// ---------------------------------------------------------------------------
__global__ void __launch_bounds__(256) out_kernel(
    const float* __restrict__ Wo, float* __restrict__ out)
{
    __shared__ float Xs[64][20];
    __shared__ float Ws[16][64];

    const int tid = threadIdx.x;
    const int tx = tid & 15, ty = tid >> 4;
    const int m0 = blockIdx.y * 64, n0 = blockIdx.x * 64;

    const int lr = tid >> 2;
    const int lk = (tid & 3) * 4;
    const int wr = tid >> 4;
    const int wn = (tid & 15) * 4;

    float acc[4][4];
#pragma unroll
    for (int r = 0; r < 4; r++)
#pragma unroll
        for (int c = 0; c < 4; c++) acc[r][c] = 0.f;

    for (int k0 = 0; k0 < DIMM; k0 += 16) {
        float4 xv = *(const float4*)(g_O + (size_t)(m0 + lr) * DIMM + k0 + lk);
        float4 wv = *(const float4*)(Wo + (size_t)(k0 + wr) * DIMM + n0 + wn);
        __syncthreads();
        *(float4*)&Xs[lr][lk] = xv;
        *(float4*)&Ws[wr][wn] = wv;
        __syncthreads();
#pragma unroll
        for (int kk = 0; kk < 16; kk++) {
            float a0 = Xs[ty * 4 + 0][kk];
            float a1 = Xs[ty * 4 + 1][kk];
            float a2 = Xs[ty * 4 + 2][kk];
            float a3 = Xs[ty * 4 + 3][kk];
            float4 bv = *(float4*)&Ws[kk][tx * 4];
            acc[0][0] += a0 * bv.x; acc[0][1] += a0 * bv.y; acc[0][2] += a0 * bv.z; acc[0][3] += a0 * bv.w;
            acc[1][0] += a1 * bv.x; acc[1][1] += a1 * bv.y; acc[1][2] += a1 * bv.z; acc[1][3] += a1 * bv.w;
            acc[2][0] += a2 * bv.x; acc[2][1] += a2 * bv.y; acc[2][2] += a2 * bv.z; acc[2][3] += a2 * bv.w;
            acc[3][0] += a3 * bv.x; acc[3][1] += a3 * bv.y; acc[3][2] += a3 * bv.z; acc[3][3] += a3 * bv.w;
        }
    }

#pragma unroll
    for (int r = 0; r < 4; r++) {
        const int m = m0 + ty * 4 + r;
#pragma unroll
        for (int c = 0; c < 4; c++) {
            out[(size_t)m * DIMM + n0 + tx * 4 + c] = acc[r][c];
        }
    }
}

// ---------------------------------------------------------------------------
extern "C" void kernel_launch(void* const* d_in, const int* in_sizes, int n_in,
                              void* d_out, int out_size)
{
    const float* x  = (const float*)d_in[0];
    const float* Wq = (const float*)d_in[1];
    const float* Wk = (const float*)d_in[2];
    const float* Wv = (const float*)d_in[3];
    const float* Wo = (const float*)d_in[4];
    const float* Wg = (const float*)d_in[5];
    const float* bg = (const float*)d_in[6];

    cudaFuncSetAttribute(attn_kernel, cudaFuncAttributeMaxDynamicSharedMemorySize,
                         ATTN_SMEM_BYTES);

    proj_kernel<<<dim3(8, 32, 4), 256>>>(x, Wq, Wk, Wv, Wg, bg);
    attn_kernel<<<dim3(16, 8, 2), 256, ATTN_SMEM_BYTES>>>();
    out_kernel<<<dim3(8, 32), 256>>>(Wo, (float*)d_out);
}

// round 3
// speedup vs baseline: 1.3416x; 1.3416x over previous
#include <cuda_runtime.h>
#include <cuda_bf16.h>
#include <math.h>
#include <stdint.h>

// Problem constants
#define BATCH 2
#define TSEQ  1024
#define DIMM  512
#define NHEAD 8
#define DKH   64
#define NROWS (BATCH * TSEQ)   // 2048

// ---------------------------------------------------------------------------
// Scratch (__device__ globals; allocation-free rule)
// ---------------------------------------------------------------------------
__device__ __align__(16) float g_Q[NROWS * DIMM];
__device__ __align__(16) float g_K[NROWS * DIMM];
__device__ __align__(16) float g_V[NROWS * DIMM];
__device__ __align__(16) float g_G[NROWS * DIMM];
__device__ __align__(16) float g_O[NROWS * DIMM];

__device__ __align__(16) __nv_bfloat16 g_Xhi[NROWS * DIMM];
__device__ __align__(16) __nv_bfloat16 g_Xlo[NROWS * DIMM];
__device__ __align__(16) __nv_bfloat16 g_Ohi[NROWS * DIMM];
__device__ __align__(16) __nv_bfloat16 g_Olo[NROWS * DIMM];
// transposed weights [n][k] (K-major); 4 projection weights + Wo
__device__ __align__(16) __nv_bfloat16 g_Wthi[4 * DIMM * DIMM];
__device__ __align__(16) __nv_bfloat16 g_Wtlo[4 * DIMM * DIMM];
__device__ __align__(16) __nv_bfloat16 g_Wothi[DIMM * DIMM];
__device__ __align__(16) __nv_bfloat16 g_Wotlo[DIMM * DIMM];

// ---------------------------------------------------------------------------
// helpers
// ---------------------------------------------------------------------------
__device__ __forceinline__ uint32_t smem_u32(const void* p) {
    uint32_t a;
    asm("{ .reg .u64 t; cvta.to.shared.u64 t, %1; cvt.u32.u64 %0, t; }" : "=r"(a) : "l"(p));
    return a;
}
__device__ __forceinline__ void cp_async16(uint32_t dst, const void* src) {
    asm volatile("cp.async.cg.shared.global [%0], [%1], 16;" :: "r"(dst), "l"(src));
}
__device__ __forceinline__ void cp_commit() {
    asm volatile("cp.async.commit_group;" ::: "memory");
}
template <int N>
__device__ __forceinline__ void cp_wait() {
    asm volatile("cp.async.wait_group %0;" :: "n"(N) : "memory");
}
__device__ __forceinline__ void mma16816(float& c0, float& c1, float& c2, float& c3,
                                         uint32_t a0, uint32_t a1, uint32_t a2, uint32_t a3,
                                         uint32_t b0, uint32_t b1) {
    asm volatile(
        "mma.sync.aligned.m16n8k16.row.col.f32.bf16.bf16.f32 "
        "{%0,%1,%2,%3}, {%4,%5,%6,%7}, {%8,%9}, {%0,%1,%2,%3};"
        : "+f"(c0), "+f"(c1), "+f"(c2), "+f"(c3)
        : "r"(a0), "r"(a1), "r"(a2), "r"(a3), "r"(b0), "r"(b1));
}

__device__ __forceinline__ void split_bf16(float v, __nv_bfloat16& h, __nv_bfloat16& l) {
    h = __float2bfloat16(v);
    l = __float2bfloat16(v - __bfloat162float(h));
}

// ---------------------------------------------------------------------------
// split kernels
// ---------------------------------------------------------------------------
__global__ void __launch_bounds__(256) split_kernel(const float* __restrict__ src_ext, int which)
{
    const float* __restrict__ src = which ? g_O : src_ext;
    __nv_bfloat16* __restrict__ hi = which ? g_Ohi : g_Xhi;
    __nv_bfloat16* __restrict__ lo = which ? g_Olo : g_Xlo;
    int i4 = (blockIdx.x * 256 + threadIdx.x) * 4;
    float4 v = *(const float4*)(src + i4);
    __nv_bfloat16 h0, h1, h2, h3, l0, l1, l2, l3;
    split_bf16(v.x, h0, l0); split_bf16(v.y, h1, l1);
    split_bf16(v.z, h2, l2); split_bf16(v.w, h3, l3);
    *(__nv_bfloat162*)(hi + i4)     = __halves2bfloat162(h0, h1);
    *(__nv_bfloat162*)(hi + i4 + 2) = __halves2bfloat162(h2, h3);
    *(__nv_bfloat162*)(lo + i4)     = __halves2bfloat162(l0, l1);
    *(__nv_bfloat162*)(lo + i4 + 2) = __halves2bfloat162(l2, l3);
}

__global__ void __launch_bounds__(256) wsplit_kernel(
    const float* __restrict__ Wq, const float* __restrict__ Wk,
    const float* __restrict__ Wv, const float* __restrict__ Wg,
    const float* __restrict__ Wo)
{
    __shared__ float t[32][33];
    const int w = blockIdx.z;
    const float* __restrict__ W = (w == 0) ? Wq : (w == 1) ? Wk : (w == 2) ? Wv : (w == 3) ? Wg : Wo;
    __nv_bfloat16* __restrict__ Hi = (w < 4) ? (g_Wthi + (size_t)w * DIMM * DIMM) : g_Wothi;
    __nv_bfloat16* __restrict__ Lo = (w < 4) ? (g_Wtlo + (size_t)w * DIMM * DIMM) : g_Wotlo;

    const int tx = threadIdx.x & 31, ty = threadIdx.x >> 5;
    const int n0 = blockIdx.x * 32, k0 = blockIdx.y * 32;
#pragma unroll
    for (int j = 0; j < 4; j++)
        t[ty + 8 * j][tx] = W[(size_t)(k0 + ty + 8 * j) * DIMM + n0 + tx];
    __syncthreads();
#pragma unroll
    for (int j = 0; j < 4; j++) {
        float v = t[tx][ty + 8 * j];
        __nv_bfloat16 h, l; split_bf16(v, h, l);
        size_t o = (size_t)(n0 + ty + 8 * j) * DIMM + k0 + tx;
        Hi[o] = h; Lo[o] = l;
    }
}

// ---------------------------------------------------------------------------
// split-bf16 HMMA GEMM: C[128,128] tile of A[2048,512] x W^T[512(n),512(k)]
// 256 threads = 8 warps (2 m x 4 n), warp tile 64x32, K chunk 32, 2-stage cp.async
// smem row padded to 40 bf16 (80B) -> conflict-free quad LDS pattern
// mode: 0 none, 1 relu, 2 sigmoid(+bias)
// ---------------------------------------------------------------------------
#define PADK 40
#define BUF_ELEMS (128 * PADK)                 // 5120 bf16 per buffer
#define STAGE_ELEMS (4 * BUF_ELEMS)            // Ahi,Alo,Bhi,Blo
#define GEMM_SMEM_BYTES (2 * STAGE_ELEMS * 2)  // 81920

__device__ __forceinline__ void mma_gemm_tile(
    const __nv_bfloat16* __restrict__ Ahi, const __nv_bfloat16* __restrict__ Alo,
    const __nv_bfloat16* __restrict__ Bhi, const __nv_bfloat16* __restrict__ Blo,
    float* __restrict__ Cout, const float* __restrict__ bias, int mode,
    int m0, int n0)
{
    extern __shared__ __nv_bfloat16 sm[];
    const uint32_t smb = smem_u32(sm);

    const int tid = threadIdx.x;
    const int wid = tid >> 5;
    const int lane = tid & 31;
    const int wm = wid >> 2;          // 0..1
    const int wn = wid & 3;           // 0..3
    const int gid = lane >> 2;        // 0..7
    const int qid = lane & 3;         // 0..3

    float c[4][4][4];
#pragma unroll
    for (int i = 0; i < 4; i++)
#pragma unroll
        for (int j = 0; j < 4; j++)
#pragma unroll
            for (int k = 0; k < 4; k++) c[i][j][k] = 0.f;

    // prefetch lambda-ish macro: 8 cp.async per thread per chunk
    const int lrow = tid >> 2;            // reuse: id = tid + t*256
    // chunk loader
    auto prefetch = [&](int chunk, int stage) {
        const int k0 = chunk * 32;
#pragma unroll
        for (int t = 0; t < 2; t++) {
            int id = tid + t * 256;       // 0..511
            int row = id >> 2, seg = id & 3;
            uint32_t soff = (uint32_t)(row * PADK + seg * 8) * 2;  // bytes
            uint32_t sb = smb + (uint32_t)stage * (STAGE_ELEMS * 2) + soff;
            size_t ao = (size_t)(m0 + row) * DIMM + k0 + seg * 8;
            size_t bo = (size_t)(n0 + row) * DIMM + k0 + seg * 8;
            cp_async16(sb + 0 * (BUF_ELEMS * 2), Ahi + ao);
            cp_async16(sb + 1 * (BUF_ELEMS * 2), Alo + ao);
            cp_async16(sb + 2 * (BUF_ELEMS * 2), Bhi + bo);
            cp_async16(sb + 3 * (BUF_ELEMS * 2), Blo + bo);
        }
        cp_commit();
    };

    prefetch(0, 0);

    for (int chunk = 0; chunk < 16; chunk++) {
        const int stage = chunk & 1;
        if (chunk + 1 < 16) {
            prefetch(chunk + 1, stage ^ 1);
            cp_wait<1>();
        } else {
            cp_wait<0>();
        }
        __syncthreads();

        const __nv_bfloat16* sA_hi = sm + stage * STAGE_ELEMS;
        const __nv_bfloat16* sA_lo = sA_hi + BUF_ELEMS;
        const __nv_bfloat16* sB_hi = sA_hi + 2 * BUF_ELEMS;
        const __nv_bfloat16* sB_lo = sA_hi + 3 * BUF_ELEMS;

#pragma unroll
        for (int ks = 0; ks < 2; ks++) {
            const int kq = ks * 16 + qid * 2;
            uint32_t ahi[4][4], alo[4][4];
#pragma unroll
            for (int mf = 0; mf < 4; mf++) {
                int r = wm * 64 + mf * 16 + gid;
                const __nv_bfloat16* ph = sA_hi + r * PADK + kq;
                const __nv_bfloat16* pl = sA_lo + r * PADK + kq;
                ahi[mf][0] = *(const uint32_t*)(ph);
                ahi[mf][1] = *(const uint32_t*)(ph + 8 * PADK);
                ahi[mf][2] = *(const uint32_t*)(ph + 8);
                ahi[mf][3] = *(const uint32_t*)(ph + 8 * PADK + 8);
                alo[mf][0] = *(const uint32_t*)(pl);
                alo[mf][1] = *(const uint32_t*)(pl + 8 * PADK);
                alo[mf][2] = *(const uint32_t*)(pl + 8);
                alo[mf][3] = *(const uint32_t*)(pl + 8 * PADK + 8);
            }
#pragma unroll
            for (int nf = 0; nf < 4; nf++) {
                int n = wn * 32 + nf * 8 + gid;
                const __nv_bfloat16* pbh = sB_hi + n * PADK + kq;
                const __nv_bfloat16* pbl = sB_lo + n * PADK + kq;
                uint32_t bh0 = *(const uint32_t*)(pbh);
                uint32_t bh1 = *(const uint32_t*)(pbh + 8);
                uint32_t bl0 = *(const uint32_t*)(pbl);
                uint32_t bl1 = *(const uint32_t*)(pbl + 8);
#pragma unroll
                for (int mf = 0; mf < 4; mf++) {
                    mma16816(c[mf][nf][0], c[mf][nf][1], c[mf][nf][2], c[mf][nf][3],
                             ahi[mf][0], ahi[mf][1], ahi[mf][2], ahi[mf][3], bh0, bh1);
                    mma16816(c[mf][nf][0], c[mf][nf][1], c[mf][nf][2], c[mf][nf][3],
                             ahi[mf][0], ahi[mf][1], ahi[mf][2], ahi[mf][3], bl0, bl1);
                    mma16816(c[mf][nf][0], c[mf][nf][1], c[mf][nf][2], c[mf][nf][3],
                             alo[mf][0], alo[mf][1], alo[mf][2], alo[mf][3], bh0, bh1);
                }
            }
        }
        __syncthreads();
    }

    // epilogue: c0,c1 at (row=gid, col=qid*2+{0,1}); c2,c3 at row+8
#pragma unroll
    for (int mf = 0; mf < 4; mf++) {
#pragma unroll
        for (int nf = 0; nf < 4; nf++) {
            int m = m0 + wm * 64 + mf * 16 + gid;
            int n = n0 + wn * 32 + nf * 8 + qid * 2;
            float v0 = c[mf][nf][0], v1 = c[mf][nf][1];
            float v2 = c[mf][nf][2], v3 = c[mf][nf][3];
            if (mode == 1) {
                v0 = fmaxf(v0, 0.f); v1 = fmaxf(v1, 0.f);
                v2 = fmaxf(v2, 0.f); v3 = fmaxf(v3, 0.f);
            } else if (mode == 2) {
                float b0 = bias[n], b1 = bias[n + 1];
                v0 = 1.f / (1.f + expf(-(v0 + b0)));
                v1 = 1.f / (1.f + expf(-(v1 + b1)));
                v2 = 1.f / (1.f + expf(-(v2 + b0)));
                v3 = 1.f / (1.f + expf(-(v3 + b1)));
            }
            *(float2*)(Cout + (size_t)m * DIMM + n)       = make_float2(v0, v1);
            *(float2*)(Cout + (size_t)(m + 8) * DIMM + n) = make_float2(v2, v3);
        }
    }
}

__global__ void __launch_bounds__(256) mma_proj_kernel(const float* __restrict__ bg)
{
    const int zi = blockIdx.z;
    const __nv_bfloat16* Bh = g_Wthi + (size_t)zi * DIMM * DIMM;
    const __nv_bfloat16* Bl = g_Wtlo + (size_t)zi * DIMM * DIMM;
    float* out = (zi == 0) ? g_Q : (zi == 1) ? g_K : (zi == 2) ? g_V : g_G;
    const int mode = (zi <= 1) ? 1 : (zi == 3 ? 2 : 0);
    mma_gemm_tile(g_Xhi, g_Xlo, Bh, Bl, out, (zi == 3) ? bg : nullptr, mode,
                  blockIdx.y * 128, blockIdx.x * 128);
}

__global__ void __launch_bounds__(256) mma_out_kernel(float* __restrict__ out)
{
    mma_gemm_tile(g_Ohi, g_Olo, g_Wothi, g_Wotlo, out, nullptr, 0,
                  blockIdx.y * 128, blockIdx.x * 128);
}

// ---------------------------------------------------------------------------
// cosformer causal attention (quadratic tiled form, fp32) — proven in R1
// ---------------------------------------------------------------------------
#define ATTN_SMEM_FLOATS (3 * 64 * 65 + 64 * 64)
#define ATTN_SMEM_BYTES  (ATTN_SMEM_FLOATS * 4)

__global__ void __launch_bounds__(256) attn_kernel()
{
    extern __shared__ float smf[];
    float (*Qs)[65] = (float(*)[65])smf;
    float (*Ks)[65] = (float(*)[65])(smf + 64 * 65);
    float (*Ss)[65] = (float(*)[65])(smf + 2 * 64 * 65);
    float (*Vs)[64] = (float(*)[64])(smf + 3 * 64 * 65);
    __shared__ float cq[64], sq[64], ck[64], sk[64];

    const int i = 15 - blockIdx.x;   // longest blocks first
    const int h = blockIdx.y;
    const int b = blockIdx.z;
    const int tid = threadIdx.x;
    const int tx = tid & 15, ty = tid >> 4;

    const int lrow = tid >> 4;
    const int lcol = (tid & 15) * 4;
    const float ANG = (float)(3.14159265358979323846 / 2048.0);

    {
        const float* Qg = g_Q + ((size_t)(b * TSEQ + i * 64)) * DIMM + h * DKH;
#pragma unroll
        for (int rr = 0; rr < 4; rr++) {
            int row = lrow + rr * 16;
            float4 v = *(const float4*)(Qg + (size_t)row * DIMM + lcol);
            Qs[row][lcol + 0] = v.x; Qs[row][lcol + 1] = v.y;
            Qs[row][lcol + 2] = v.z; Qs[row][lcol + 3] = v.w;
        }
        if (tid < 64) {
            float s, c;
            sincosf((float)(i * 64 + tid) * ANG, &s, &c);
            cq[tid] = c; sq[tid] = s;
        }
    }

    float acc[4][4];
#pragma unroll
    for (int r = 0; r < 4; r++)
#pragma unroll
        for (int c = 0; c < 4; c++) acc[r][c] = 0.f;
    float zacc[4] = {0.f, 0.f, 0.f, 0.f};

    for (int j = 0; j <= i; j++) {
        __syncthreads();
        const float* Kg = g_K + ((size_t)(b * TSEQ + j * 64)) * DIMM + h * DKH;
        const float* Vg = g_V + ((size_t)(b * TSEQ + j * 64)) * DIMM + h * DKH;
#pragma unroll
        for (int rr = 0; rr < 4; rr++) {
            int row = lrow + rr * 16;
            float4 kv = *(const float4*)(Kg + (size_t)row * DIMM + lcol);
            Ks[row][lcol + 0] = kv.x; Ks[row][lcol + 1] = kv.y;
            Ks[row][lcol + 2] = kv.z; Ks[row][lcol + 3] = kv.w;
            float4 vv = *(const float4*)(Vg + (size_t)row * DIMM + lcol);
            *(float4*)&Vs[row][lcol] = vv;
        }
        if (tid < 64) {
            float s, c;
            sincosf((float)(j * 64 + tid) * ANG, &s, &c);
            ck[tid] = c; sk[tid] = s;
        }
        __syncthreads();

        float sacc[4][4];
#pragma unroll
        for (int r = 0; r < 4; r++)
#pragma unroll
            for (int c = 0; c < 4; c++) sacc[r][c] = 0.f;
#pragma unroll 16
        for (int d = 0; d < 64; d++) {
            float a0 = Qs[ty * 4 + 0][d];
            float a1 = Qs[ty * 4 + 1][d];
            float a2 = Qs[ty * 4 + 2][d];
            float a3 = Qs[ty * 4 + 3][d];
            float b0 = Ks[tx * 4 + 0][d];
            float b1 = Ks[tx * 4 + 1][d];
            float b2 = Ks[tx * 4 + 2][d];
            float b3 = Ks[tx * 4 + 3][d];
            sacc[0][0] += a0 * b0; sacc[0][1] += a0 * b1; sacc[0][2] += a0 * b2; sacc[0][3] += a0 * b3;
            sacc[1][0] += a1 * b0; sacc[1][1] += a1 * b1; sacc[1][2] += a1 * b2; sacc[1][3] += a1 * b3;
            sacc[2][0] += a2 * b0; sacc[2][1] += a2 * b1; sacc[2][2] += a2 * b2; sacc[2][3] += a2 * b3;
            sacc[3][0] += a3 * b0; sacc[3][1] += a3 * b1; sacc[3][2] += a3 * b2; sacc[3][3] += a3 * b3;
        }

        const bool diag = (j == i);
#pragma unroll
        for (int r = 0; r < 4; r++) {
            const int tq = ty * 4 + r;
            const float cc = cq[tq], ss = sq[tq];
#pragma unroll
            for (int c = 0; c < 4; c++) {
                const int ts = tx * 4 + c;
                float w = cc * ck[ts] + ss * sk[ts];
                float sv = sacc[r][c] * w;
                if (diag && ts > tq) sv = 0.f;
                zacc[r] += sv;
                Ss[tq][ts] = sv;
            }
        }
        __syncthreads();

#pragma unroll 8
        for (int ts = 0; ts < 64; ts++) {
            float a0 = Ss[ty * 4 + 0][ts];
            float a1 = Ss[ty * 4 + 1][ts];
            float a2 = Ss[ty * 4 + 2][ts];
            float a3 = Ss[ty * 4 + 3][ts];
            float4 bv = *(float4*)&Vs[ts][tx * 4];
            acc[0][0] += a0 * bv.x; acc[0][1] += a0 * bv.y; acc[0][2] += a0 * bv.z; acc[0][3] += a0 * bv.w;
            acc[1][0] += a1 * bv.x; acc[1][1] += a1 * bv.y; acc[1][2] += a1 * bv.z; acc[1][3] += a1 * bv.w;
            acc[2][0] += a2 * bv.x; acc[2][1] += a2 * bv.y; acc[2][2] += a2 * bv.z; acc[2][3] += a2 * bv.w;
            acc[3][0] += a3 * bv.x; acc[3][1] += a3 * bv.y; acc[3][2] += a3 * bv.z; acc[3][3] += a3 * bv.w;
        }
    }

    float zinv[4];
#pragma unroll
    for (int r = 0; r < 4; r++) {
        float z = zacc[r];
        z += __shfl_xor_sync(0xffffffffu, z, 1);
        z += __shfl_xor_sync(0xffffffffu, z, 2);
        z += __shfl_xor_sync(0xffffffffu, z, 4);
        z += __shfl_xor_sync(0xffffffffu, z, 8);
        zinv[r] = 1.f / fmaxf(z, 1e-6f);
    }

    float* Og = g_O + ((size_t)(b * TSEQ + i * 64)) * DIMM + h * DKH;
    const float* Gg = g_G + ((size_t)(b * TSEQ + i * 64)) * DIMM + h * DKH;
#pragma unroll
    for (int r = 0; r < 4; r++) {
#pragma unroll
        for (int c = 0; c < 4; c++) {
            const int off = (ty * 4 + r) * DIMM + tx * 4 + c;
            Og[off] = acc[r][c] * zinv[r] * Gg[off];
        }
    }
}

// ---------------------------------------------------------------------------
extern "C" void kernel_launch(void* const* d_in, const int* in_sizes, int n_in,
                              void* d_out, int out_size)
{
    const float* x  = (const float*)d_in[0];
    const float* Wq = (const float*)d_in[1];
    const float* Wk = (const float*)d_in[2];
    const float* Wv = (const float*)d_in[3];
    const float* Wo = (const float*)d_in[4];
    const float* Wg = (const float*)d_in[5];
    const float* bg = (const float*)d_in[6];

    cudaFuncSetAttribute(attn_kernel, cudaFuncAttributeMaxDynamicSharedMemorySize, ATTN_SMEM_BYTES);
    cudaFuncSetAttribute(mma_proj_kernel, cudaFuncAttributeMaxDynamicSharedMemorySize, GEMM_SMEM_BYTES);
    cudaFuncSetAttribute(mma_out_kernel, cudaFuncAttributeMaxDynamicSharedMemorySize, GEMM_SMEM_BYTES);

    split_kernel<<<NROWS * DIMM / 1024, 256>>>(x, 0);
    wsplit_kernel<<<dim3(16, 16, 5), 256>>>(Wq, Wk, Wv, Wg, Wo);
    mma_proj_kernel<<<dim3(4, 16, 4), 256, GEMM_SMEM_BYTES>>>(bg);
    attn_kernel<<<dim3(16, 8, 2), 256, ATTN_SMEM_BYTES>>>();
    split_kernel<<<NROWS * DIMM / 1024, 256>>>(nullptr, 1);
    mma_out_kernel<<<dim3(4, 16), 256, GEMM_SMEM_BYTES>>>((float*)d_out);
}

// round 4
// speedup vs baseline: 2.1972x; 1.6378x over previous
#include <cuda_runtime.h>
#include <cuda_bf16.h>
#include <math.h>
#include <stdint.h>

// Problem constants
#define BATCH 2
#define TSEQ  1024
#define DIMM  512
#define NHEAD 8
#define DKH   64
#define NROWS (BATCH * TSEQ)   // 2048

// ---------------------------------------------------------------------------
// Scratch (__device__ globals)
// ---------------------------------------------------------------------------
__device__ __align__(16) float g_G[NROWS * DIMM];

__device__ __align__(16) __nv_bfloat16 g_Xhi[NROWS * DIMM];
__device__ __align__(16) __nv_bfloat16 g_Xlo[NROWS * DIMM];
__device__ __align__(16) __nv_bfloat16 g_Qh[NROWS * DIMM];
__device__ __align__(16) __nv_bfloat16 g_Ql[NROWS * DIMM];
__device__ __align__(16) __nv_bfloat16 g_Kh[NROWS * DIMM];
__device__ __align__(16) __nv_bfloat16 g_Kl[NROWS * DIMM];
// V transposed: [(b*8+h)*64 + d][t]
__device__ __align__(16) __nv_bfloat16 g_Vth[NROWS * DIMM];
__device__ __align__(16) __nv_bfloat16 g_Vtl[NROWS * DIMM];
__device__ __align__(16) __nv_bfloat16 g_Ohi[NROWS * DIMM];
__device__ __align__(16) __nv_bfloat16 g_Olo[NROWS * DIMM];
// transposed weights [n][k] (K-major); 4 projection weights + Wo
__device__ __align__(16) __nv_bfloat16 g_Wthi[4 * DIMM * DIMM];
__device__ __align__(16) __nv_bfloat16 g_Wtlo[4 * DIMM * DIMM];
__device__ __align__(16) __nv_bfloat16 g_Wothi[DIMM * DIMM];
__device__ __align__(16) __nv_bfloat16 g_Wotlo[DIMM * DIMM];

// ---------------------------------------------------------------------------
// helpers
// ---------------------------------------------------------------------------
__device__ __forceinline__ uint32_t smem_u32(const void* p) {
    uint32_t a;
    asm("{ .reg .u64 t; cvta.to.shared.u64 t, %1; cvt.u32.u64 %0, t; }" : "=r"(a) : "l"(p));
    return a;
}
__device__ __forceinline__ void cp_async16(uint32_t dst, const void* src) {
    asm volatile("cp.async.cg.shared.global [%0], [%1], 16;" :: "r"(dst), "l"(src));
}
__device__ __forceinline__ void cp_commit() {
    asm volatile("cp.async.commit_group;" ::: "memory");
}
template <int N>
__device__ __forceinline__ void cp_wait() {
    asm volatile("cp.async.wait_group %0;" :: "n"(N) : "memory");
}
__device__ __forceinline__ void mma16816(float* c,
                                         uint32_t a0, uint32_t a1, uint32_t a2, uint32_t a3,
                                         uint32_t b0, uint32_t b1) {
    asm volatile(
        "mma.sync.aligned.m16n8k16.row.col.f32.bf16.bf16.f32 "
        "{%0,%1,%2,%3}, {%4,%5,%6,%7}, {%8,%9}, {%0,%1,%2,%3};"
        : "+f"(c[0]), "+f"(c[1]), "+f"(c[2]), "+f"(c[3])
        : "r"(a0), "r"(a1), "r"(a2), "r"(a3), "r"(b0), "r"(b1));
}
__device__ __forceinline__ void split_bf16(float v, __nv_bfloat16& h, __nv_bfloat16& l) {
    h = __float2bfloat16(v);
    l = __float2bfloat16(v - __bfloat162float(h));
}
__device__ __forceinline__ uint32_t pack2(__nv_bfloat16 a, __nv_bfloat16 b) {
    __nv_bfloat162 t = __halves2bfloat162(a, b);
    return *(uint32_t*)&t;
}
__device__ __forceinline__ uint32_t ld32s(const __nv_bfloat16* p) {
    return *(const uint32_t*)p;
}

// ---------------------------------------------------------------------------
// split kernels
// ---------------------------------------------------------------------------
__global__ void __launch_bounds__(256) split_kernel(const float* __restrict__ src)
{
    int i4 = (blockIdx.x * 256 + threadIdx.x) * 4;
    float4 v = *(const float4*)(src + i4);
    __nv_bfloat16 h0, h1, h2, h3, l0, l1, l2, l3;
    split_bf16(v.x, h0, l0); split_bf16(v.y, h1, l1);
    split_bf16(v.z, h2, l2); split_bf16(v.w, h3, l3);
    *(__nv_bfloat162*)(g_Xhi + i4)     = __halves2bfloat162(h0, h1);
    *(__nv_bfloat162*)(g_Xhi + i4 + 2) = __halves2bfloat162(h2, h3);
    *(__nv_bfloat162*)(g_Xlo + i4)     = __halves2bfloat162(l0, l1);
    *(__nv_bfloat162*)(g_Xlo + i4 + 2) = __halves2bfloat162(l2, l3);
}

__global__ void __launch_bounds__(256) wsplit_kernel(
    const float* __restrict__ Wq, const float* __restrict__ Wk,
    const float* __restrict__ Wv, const float* __restrict__ Wg,
    const float* __restrict__ Wo)
{
    __shared__ float t[32][33];
    const int w = blockIdx.z;
    const float* __restrict__ W = (w == 0) ? Wq : (w == 1) ? Wk : (w == 2) ? Wv : (w == 3) ? Wg : Wo;
    __nv_bfloat16* __restrict__ Hi = (w < 4) ? (g_Wthi + (size_t)w * DIMM * DIMM) : g_Wothi;
    __nv_bfloat16* __restrict__ Lo = (w < 4) ? (g_Wtlo + (size_t)w * DIMM * DIMM) : g_Wotlo;

    const int tx = threadIdx.x & 31, ty = threadIdx.x >> 5;
    const int n0 = blockIdx.x * 32, k0 = blockIdx.y * 32;
#pragma unroll
    for (int j = 0; j < 4; j++)
        t[ty + 8 * j][tx] = W[(size_t)(k0 + ty + 8 * j) * DIMM + n0 + tx];
    __syncthreads();
#pragma unroll
    for (int j = 0; j < 4; j++) {
        float v = t[tx][ty + 8 * j];
        __nv_bfloat16 h, l; split_bf16(v, h, l);
        size_t o = (size_t)(n0 + ty + 8 * j) * DIMM + k0 + tx;
        Hi[o] = h; Lo[o] = l;
    }
}

// ---------------------------------------------------------------------------
// split-bf16 HMMA GEMM core (from R3, parameterized epilogue)
// mode: 0 plain float out, 1 relu->bf16 hi/lo, 2 split->transposed Vt, 3 sigmoid->float
// ---------------------------------------------------------------------------
#define PADK 40
#define BUF_ELEMS (128 * PADK)
#define STAGE_ELEMS (4 * BUF_ELEMS)
#define GEMM_SMEM_BYTES (2 * STAGE_ELEMS * 2)  // 81920

__device__ __forceinline__ void mma_gemm_tile(
    const __nv_bfloat16* __restrict__ Ahi, const __nv_bfloat16* __restrict__ Alo,
    const __nv_bfloat16* __restrict__ Bhi, const __nv_bfloat16* __restrict__ Blo,
    int mode, int m0, int n0,
    float* __restrict__ fout, __nv_bfloat16* __restrict__ ohi,
    __nv_bfloat16* __restrict__ olo, const float* __restrict__ bias)
{
    extern __shared__ __nv_bfloat16 sm[];
    const uint32_t smb = smem_u32(sm);

    const int tid = threadIdx.x;
    const int wid = tid >> 5;
    const int lane = tid & 31;
    const int wm = wid >> 2;
    const int wn = wid & 3;
    const int gid = lane >> 2;
    const int qid = lane & 3;

    float c[4][4][4];
#pragma unroll
    for (int i = 0; i < 4; i++)
#pragma unroll
        for (int j = 0; j < 4; j++)
#pragma unroll
            for (int k = 0; k < 4; k++) c[i][j][k] = 0.f;

    auto prefetch = [&](int chunk, int stage) {
        const int k0 = chunk * 32;
#pragma unroll
        for (int t = 0; t < 2; t++) {
            int id = tid + t * 256;
            int row = id >> 2, seg = id & 3;
            uint32_t soff = (uint32_t)(row * PADK + seg * 8) * 2;
            uint32_t sb = smb + (uint32_t)stage * (STAGE_ELEMS * 2) + soff;
            size_t ao = (size_t)(m0 + row) * DIMM + k0 + seg * 8;
            size_t bo = (size_t)(n0 + row) * DIMM + k0 + seg * 8;
            cp_async16(sb + 0 * (BUF_ELEMS * 2), Ahi + ao);
            cp_async16(sb + 1 * (BUF_ELEMS * 2), Alo + ao);
            cp_async16(sb + 2 * (BUF_ELEMS * 2), Bhi + bo);
            cp_async16(sb + 3 * (BUF_ELEMS * 2), Blo + bo);
        }
        cp_commit();
    };

    prefetch(0, 0);

    for (int chunk = 0; chunk < 16; chunk++) {
        const int stage = chunk & 1;
        if (chunk + 1 < 16) {
            prefetch(chunk + 1, stage ^ 1);
            cp_wait<1>();
        } else {
            cp_wait<0>();
        }
        __syncthreads();

        const __nv_bfloat16* sA_hi = sm + stage * STAGE_ELEMS;
        const __nv_bfloat16* sA_lo = sA_hi + BUF_ELEMS;
        const __nv_bfloat16* sB_hi = sA_hi + 2 * BUF_ELEMS;
        const __nv_bfloat16* sB_lo = sA_hi + 3 * BUF_ELEMS;

#pragma unroll
        for (int ks = 0; ks < 2; ks++) {
            const int kq = ks * 16 + qid * 2;
            uint32_t ahi[4][4], alo[4][4];
#pragma unroll
            for (int mf = 0; mf < 4; mf++) {
                int r = wm * 64 + mf * 16 + gid;
                const __nv_bfloat16* ph = sA_hi + r * PADK + kq;
                const __nv_bfloat16* pl = sA_lo + r * PADK + kq;
                ahi[mf][0] = ld32s(ph);
                ahi[mf][1] = ld32s(ph + 8 * PADK);
                ahi[mf][2] = ld32s(ph + 8);
                ahi[mf][3] = ld32s(ph + 8 * PADK + 8);
                alo[mf][0] = ld32s(pl);
                alo[mf][1] = ld32s(pl + 8 * PADK);
                alo[mf][2] = ld32s(pl + 8);
                alo[mf][3] = ld32s(pl + 8 * PADK + 8);
            }
#pragma unroll
            for (int nf = 0; nf < 4; nf++) {
                int n = wn * 32 + nf * 8 + gid;
                const __nv_bfloat16* pbh = sB_hi + n * PADK + kq;
                const __nv_bfloat16* pbl = sB_lo + n * PADK + kq;
                uint32_t bh0 = ld32s(pbh);
                uint32_t bh1 = ld32s(pbh + 8);
                uint32_t bl0 = ld32s(pbl);
                uint32_t bl1 = ld32s(pbl + 8);
#pragma unroll
                for (int mf = 0; mf < 4; mf++) {
                    mma16816(c[mf][nf], ahi[mf][0], ahi[mf][1], ahi[mf][2], ahi[mf][3], bh0, bh1);
                    mma16816(c[mf][nf], ahi[mf][0], ahi[mf][1], ahi[mf][2], ahi[mf][3], bl0, bl1);
                    mma16816(c[mf][nf], alo[mf][0], alo[mf][1], alo[mf][2], alo[mf][3], bh0, bh1);
                }
            }
        }
        __syncthreads();
    }

#pragma unroll
    for (int mf = 0; mf < 4; mf++) {
#pragma unroll
        for (int nf = 0; nf < 4; nf++) {
            int m = m0 + wm * 64 + mf * 16 + gid;
            int n = n0 + wn * 32 + nf * 8 + qid * 2;
            float v0 = c[mf][nf][0], v1 = c[mf][nf][1];
            float v2 = c[mf][nf][2], v3 = c[mf][nf][3];
            if (mode == 0) {
                *(float2*)(fout + (size_t)m * DIMM + n)       = make_float2(v0, v1);
                *(float2*)(fout + (size_t)(m + 8) * DIMM + n) = make_float2(v2, v3);
            } else if (mode == 1) {
                v0 = fmaxf(v0, 0.f); v1 = fmaxf(v1, 0.f);
                v2 = fmaxf(v2, 0.f); v3 = fmaxf(v3, 0.f);
                __nv_bfloat16 h0, h1, h2, h3, l0, l1, l2, l3;
                split_bf16(v0, h0, l0); split_bf16(v1, h1, l1);
                split_bf16(v2, h2, l2); split_bf16(v3, h3, l3);
                *(__nv_bfloat162*)(ohi + (size_t)m * DIMM + n)       = __halves2bfloat162(h0, h1);
                *(__nv_bfloat162*)(ohi + (size_t)(m + 8) * DIMM + n) = __halves2bfloat162(h2, h3);
                *(__nv_bfloat162*)(olo + (size_t)m * DIMM + n)       = __halves2bfloat162(l0, l1);
                *(__nv_bfloat162*)(olo + (size_t)(m + 8) * DIMM + n) = __halves2bfloat162(l2, l3);
            } else if (mode == 2) {
                // transposed: Vt[(b*8+h)*64 + d][t]
                int bb = m >> 10, tt = m & 1023;
                int hh = n >> 6, dd = n & 63;
                size_t base = ((size_t)((bb * 8 + hh) * 64 + dd)) * 1024 + tt;
                __nv_bfloat16 h0, h1, h2, h3, l0, l1, l2, l3;
                split_bf16(v0, h0, l0); split_bf16(v1, h1, l1);
                split_bf16(v2, h2, l2); split_bf16(v3, h3, l3);
                ohi[base] = h0;        olo[base] = l0;
                ohi[base + 1024] = h1; olo[base + 1024] = l1;
                ohi[base + 8] = h2;    olo[base + 8] = l2;
                ohi[base + 1032] = h3; olo[base + 1032] = l3;
            } else {
                float b0 = bias[n], b1 = bias[n + 1];
                v0 = 1.f / (1.f + expf(-(v0 + b0)));
                v1 = 1.f / (1.f + expf(-(v1 + b1)));
                v2 = 1.f / (1.f + expf(-(v2 + b0)));
                v3 = 1.f / (1.f + expf(-(v3 + b1)));
                *(float2*)(fout + (size_t)m * DIMM + n)       = make_float2(v0, v1);
                *(float2*)(fout + (size_t)(m + 8) * DIMM + n) = make_float2(v2, v3);
            }
        }
    }
}

__global__ void __launch_bounds__(256) mma_proj_kernel(const float* __restrict__ bg)
{
    const int zi = blockIdx.z;
    const __nv_bfloat16* Bh = g_Wthi + (size_t)zi * DIMM * DIMM;
    const __nv_bfloat16* Bl = g_Wtlo + (size_t)zi * DIMM * DIMM;
    const int m0 = blockIdx.y * 128, n0 = blockIdx.x * 128;
    if (zi == 0)
        mma_gemm_tile(g_Xhi, g_Xlo, Bh, Bl, 1, m0, n0, nullptr, g_Qh, g_Ql, nullptr);
    else if (zi == 1)
        mma_gemm_tile(g_Xhi, g_Xlo, Bh, Bl, 1, m0, n0, nullptr, g_Kh, g_Kl, nullptr);
    else if (zi == 2)
        mma_gemm_tile(g_Xhi, g_Xlo, Bh, Bl, 2, m0, n0, nullptr, g_Vth, g_Vtl, nullptr);
    else
        mma_gemm_tile(g_Xhi, g_Xlo, Bh, Bl, 3, m0, n0, g_G, nullptr, nullptr, bg);
}

__global__ void __launch_bounds__(256) mma_out_kernel(float* __restrict__ out)
{
    mma_gemm_tile(g_Ohi, g_Olo, g_Wothi, g_Wotlo, 0, blockIdx.y * 128, blockIdx.x * 128,
                  out, nullptr, nullptr, nullptr);
}

// ---------------------------------------------------------------------------
// HMMA cosformer attention
// CTA: 128 threads (4 warps), q-tile 64 rows, key tiles of 64, split-bf16 MMA
// ---------------------------------------------------------------------------
#define APAD 72
#define ATILE (64 * APAD)            // 4608 bf16 per tile buffer
#define AQH 0
#define AQL (ATILE)
#define AKH (2 * ATILE)              // [2] stages
#define AKL (4 * ATILE)
#define AVH (6 * ATILE)
#define AVL (8 * ATILE)
#define ATRIG_C (10 * ATILE * 2)     // byte offset of cks[2][64] floats
#define ATTN2_SMEM_BYTES (10 * ATILE * 2 + 2 * 2 * 64 * 4)

__global__ void __launch_bounds__(128) attn2_kernel()
{
    extern __shared__ __nv_bfloat16 asm_[];
    const uint32_t smb = smem_u32(asm_);
    float* cks = (float*)((char*)asm_ + ATRIG_C);
    float* sks = cks + 128;

    const int i = 15 - blockIdx.x;   // longest first
    const int h = blockIdx.y;
    const int b = blockIdx.z;
    const int tid = threadIdx.x;
    const int wid = tid >> 5;
    const int lane = tid & 31;
    const int gid = lane >> 2;
    const int qid = lane & 3;

    const int qrow0 = b * TSEQ + i * 64;          // global row base of this q tile
    const float ANG = (float)(3.14159265358979323846 / 2048.0);

    // prologue: load Q tile (hi/lo) + stage0 K/Vt
    {
#pragma unroll
        for (int t = 0; t < 4; t++) {
            int id = tid + t * 128;
            int row = id >> 3, seg = id & 7;
            size_t src = (size_t)(qrow0 + row) * DIMM + h * DKH + seg * 8;
            uint32_t so = (uint32_t)(row * APAD + seg * 8) * 2;
            cp_async16(smb + AQH * 2 + so, g_Qh + src);
            cp_async16(smb + AQL * 2 + so, g_Ql + src);
        }
    }
    auto prefetch_kv = [&](int j, int s) {
#pragma unroll
        for (int t = 0; t < 4; t++) {
            int id = tid + t * 128;
            int row = id >> 3, seg = id & 7;
            uint32_t so = (uint32_t)(row * APAD + seg * 8) * 2 + (uint32_t)s * (ATILE * 2);
            size_t ksrc = (size_t)(b * TSEQ + j * 64 + row) * DIMM + h * DKH + seg * 8;
            cp_async16(smb + AKH * 2 + so, g_Kh + ksrc);
            cp_async16(smb + AKL * 2 + so, g_Kl + ksrc);
            size_t vsrc = (size_t)((b * 8 + h) * 64 + row) * TSEQ + j * 64 + seg * 8;
            cp_async16(smb + AVH * 2 + so, g_Vth + vsrc);
            cp_async16(smb + AVL * 2 + so, g_Vtl + vsrc);
        }
    };
    prefetch_kv(0, 0);
    cp_commit();

    // per-thread query trig (rows wid*16+gid, +8)
    float cq0, sq0, cq1, sq1;
    {
        float a0 = (float)(i * 64 + wid * 16 + gid) * ANG;
        float a1 = (float)(i * 64 + wid * 16 + gid + 8) * ANG;
        sincosf(a0, &sq0, &cq0);
        sincosf(a1, &sq1, &cq1);
    }

    float oacc[8][4];
#pragma unroll
    for (int nf = 0; nf < 8; nf++)
#pragma unroll
        for (int k = 0; k < 4; k++) oacc[nf][k] = 0.f;
    float z0 = 0.f, z1 = 0.f;

    const __nv_bfloat16* Qhs = asm_ + AQH;
    const __nv_bfloat16* Qls = asm_ + AQL;

    for (int j = 0; j <= i; j++) {
        const int s = j & 1;
        cp_wait<0>();
        __syncthreads();
        if (j < i) { prefetch_kv(j + 1, s ^ 1); cp_commit(); }
        if (tid < 64) {
            float ss, cc;
            sincosf((float)(j * 64 + tid) * ANG, &ss, &cc);
            cks[s * 64 + tid] = cc;
            sks[s * 64 + tid] = ss;
        }
        __syncthreads();

        const __nv_bfloat16* Khs = asm_ + AKH + s * ATILE;
        const __nv_bfloat16* Kls = asm_ + AKL + s * ATILE;
        const __nv_bfloat16* Vhs = asm_ + AVH + s * ATILE;
        const __nv_bfloat16* Vls = asm_ + AVL + s * ATILE;

        // --- S = Q K^T ---
        float sc[8][4];
#pragma unroll
        for (int nf = 0; nf < 8; nf++)
#pragma unroll
            for (int k = 0; k < 4; k++) sc[nf][k] = 0.f;

#pragma unroll
        for (int ks = 0; ks < 4; ks++) {
            const int kq = ks * 16 + qid * 2;
            const __nv_bfloat16* ph = Qhs + (wid * 16 + gid) * APAD + kq;
            const __nv_bfloat16* pl = Qls + (wid * 16 + gid) * APAD + kq;
            uint32_t qh0 = ld32s(ph), qh1 = ld32s(ph + 8 * APAD);
            uint32_t qh2 = ld32s(ph + 8), qh3 = ld32s(ph + 8 * APAD + 8);
            uint32_t ql0 = ld32s(pl), ql1 = ld32s(pl + 8 * APAD);
            uint32_t ql2 = ld32s(pl + 8), ql3 = ld32s(pl + 8 * APAD + 8);
#pragma unroll
            for (int nf = 0; nf < 8; nf++) {
                const __nv_bfloat16* pk = Khs + (nf * 8 + gid) * APAD + kq;
                const __nv_bfloat16* pkl = Kls + (nf * 8 + gid) * APAD + kq;
                uint32_t kh0 = ld32s(pk), kh1 = ld32s(pk + 8);
                uint32_t kl0 = ld32s(pkl), kl1 = ld32s(pkl + 8);
                mma16816(sc[nf], qh0, qh1, qh2, qh3, kh0, kh1);
                mma16816(sc[nf], qh0, qh1, qh2, qh3, kl0, kl1);
                mma16816(sc[nf], ql0, ql1, ql2, ql3, kh0, kh1);
            }
        }

        // --- weight, mask, z, split to A-frags ---
        uint32_t ah[4][4], al[4][4];
        const bool diag = (j == i);
        const int lr0 = wid * 16 + gid, lr1 = lr0 + 8;
#pragma unroll
        for (int nf = 0; nf < 8; nf++) {
            const int c0 = nf * 8 + qid * 2, c1 = c0 + 1;
            float ck0 = cks[s * 64 + c0], sk0 = sks[s * 64 + c0];
            float ck1 = cks[s * 64 + c1], sk1 = sks[s * 64 + c1];
            float v0 = sc[nf][0] * (cq0 * ck0 + sq0 * sk0);
            float v1 = sc[nf][1] * (cq0 * ck1 + sq0 * sk1);
            float v2 = sc[nf][2] * (cq1 * ck0 + sq1 * sk0);
            float v3 = sc[nf][3] * (cq1 * ck1 + sq1 * sk1);
            if (diag) {
                if (c0 > lr0) v0 = 0.f;
                if (c1 > lr0) v1 = 0.f;
                if (c0 > lr1) v2 = 0.f;
                if (c1 > lr1) v3 = 0.f;
            }
            z0 += v0 + v1;
            z1 += v2 + v3;
            __nv_bfloat16 h0, h1, h2, h3, l0, l1, l2, l3;
            split_bf16(v0, h0, l0); split_bf16(v1, h1, l1);
            split_bf16(v2, h2, l2); split_bf16(v3, h3, l3);
            const int f = nf >> 1;
            if ((nf & 1) == 0) {
                ah[f][0] = pack2(h0, h1); ah[f][1] = pack2(h2, h3);
                al[f][0] = pack2(l0, l1); al[f][1] = pack2(l2, l3);
            } else {
                ah[f][2] = pack2(h0, h1); ah[f][3] = pack2(h2, h3);
                al[f][2] = pack2(l0, l1); al[f][3] = pack2(l2, l3);
            }
        }

        // --- O += S Vt^T ---
#pragma unroll
        for (int f = 0; f < 4; f++) {
            const int kq = f * 16 + qid * 2;
#pragma unroll
            for (int nf = 0; nf < 8; nf++) {
                const __nv_bfloat16* pv = Vhs + (nf * 8 + gid) * APAD + kq;
                const __nv_bfloat16* pvl = Vls + (nf * 8 + gid) * APAD + kq;
                uint32_t vh0 = ld32s(pv), vh1 = ld32s(pv + 8);
                uint32_t vl0 = ld32s(pvl), vl1 = ld32s(pvl + 8);
                mma16816(oacc[nf], ah[f][0], ah[f][1], ah[f][2], ah[f][3], vh0, vh1);
                mma16816(oacc[nf], al[f][0], al[f][1], al[f][2], al[f][3], vh0, vh1);
                mma16816(oacc[nf], ah[f][0], ah[f][1], ah[f][2], ah[f][3], vl0, vl1);
            }
        }
    }

    // z reduce over qid lanes (xor 1,2 within quad)
    z0 += __shfl_xor_sync(0xffffffffu, z0, 1);
    z0 += __shfl_xor_sync(0xffffffffu, z0, 2);
    z1 += __shfl_xor_sync(0xffffffffu, z1, 1);
    z1 += __shfl_xor_sync(0xffffffffu, z1, 2);
    const float zi0 = 1.f / fmaxf(z0, 1e-6f);
    const float zi1 = 1.f / fmaxf(z1, 1e-6f);

    const int gr0 = qrow0 + wid * 16 + gid;
    const int gr1 = gr0 + 8;
#pragma unroll
    for (int nf = 0; nf < 8; nf++) {
        const int col = h * DKH + nf * 8 + qid * 2;
        float2 g0 = *(const float2*)(g_G + (size_t)gr0 * DIMM + col);
        float2 g1 = *(const float2*)(g_G + (size_t)gr1 * DIMM + col);
        float v0 = oacc[nf][0] * zi0 * g0.x;
        float v1 = oacc[nf][1] * zi0 * g0.y;
        float v2 = oacc[nf][2] * zi1 * g1.x;
        float v3 = oacc[nf][3] * zi1 * g1.y;
        __nv_bfloat16 h0, h1, h2, h3, l0, l1, l2, l3;
        split_bf16(v0, h0, l0); split_bf16(v1, h1, l1);
        split_bf16(v2, h2, l2); split_bf16(v3, h3, l3);
        *(__nv_bfloat162*)(g_Ohi + (size_t)gr0 * DIMM + col) = __halves2bfloat162(h0, h1);
        *(__nv_bfloat162*)(g_Ohi + (size_t)gr1 * DIMM + col) = __halves2bfloat162(h2, h3);
        *(__nv_bfloat162*)(g_Olo + (size_t)gr0 * DIMM + col) = __halves2bfloat162(l0, l1);
        *(__nv_bfloat162*)(g_Olo + (size_t)gr1 * DIMM + col) = __halves2bfloat162(l2, l3);
    }
}

// ---------------------------------------------------------------------------
extern "C" void kernel_launch(void* const* d_in, const int* in_sizes, int n_in,
                              void* d_out, int out_size)
{
    const float* x  = (const float*)d_in[0];
    const float* Wq = (const float*)d_in[1];
    const float* Wk = (const float*)d_in[2];
    const float* Wv = (const float*)d_in[3];
    const float* Wo = (const float*)d_in[4];
    const float* Wg = (const float*)d_in[5];
    const float* bg = (const float*)d_in[6];

    cudaFuncSetAttribute(mma_proj_kernel, cudaFuncAttributeMaxDynamicSharedMemorySize, GEMM_SMEM_BYTES);
    cudaFuncSetAttribute(mma_out_kernel, cudaFuncAttributeMaxDynamicSharedMemorySize, GEMM_SMEM_BYTES);
    cudaFuncSetAttribute(attn2_kernel, cudaFuncAttributeMaxDynamicSharedMemorySize, ATTN2_SMEM_BYTES);

    split_kernel<<<NROWS * DIMM / 1024, 256>>>(x);
    wsplit_kernel<<<dim3(16, 16, 5), 256>>>(Wq, Wk, Wv, Wg, Wo);
    mma_proj_kernel<<<dim3(4, 16, 4), 256, GEMM_SMEM_BYTES>>>(bg);
    attn2_kernel<<<dim3(16, 8, 2), 128, ATTN2_SMEM_BYTES>>>();
    mma_out_kernel<<<dim3(4, 16), 256, GEMM_SMEM_BYTES>>>((float*)d_out);
}

// round 5
// speedup vs baseline: 2.4369x; 1.1091x over previous
#include <cuda_runtime.h>
#include <cuda_bf16.h>
#include <math.h>
#include <stdint.h>

// Problem constants
#define BATCH 2
#define TSEQ  1024
#define DIMM  512
#define NHEAD 8
#define DKH   64
#define NROWS (BATCH * TSEQ)   // 2048

// ---------------------------------------------------------------------------
// Scratch (__device__ globals)
// ---------------------------------------------------------------------------
__device__ __align__(16) float g_G[NROWS * DIMM];
__device__ __align__(16) float g_Opart0[NROWS * DIMM];
__device__ __align__(16) float g_Opart1[NROWS * DIMM];
__device__ __align__(16) float g_zpart0[NROWS * NHEAD];
__device__ __align__(16) float g_zpart1[NROWS * NHEAD];

__device__ __align__(16) __nv_bfloat16 g_Xhi[NROWS * DIMM];
__device__ __align__(16) __nv_bfloat16 g_Xlo[NROWS * DIMM];
__device__ __align__(16) __nv_bfloat16 g_Qh[NROWS * DIMM];
__device__ __align__(16) __nv_bfloat16 g_Ql[NROWS * DIMM];
__device__ __align__(16) __nv_bfloat16 g_Kh[NROWS * DIMM];
__device__ __align__(16) __nv_bfloat16 g_Kl[NROWS * DIMM];
// V transposed: [(b*8+h)*64 + d][t]
__device__ __align__(16) __nv_bfloat16 g_Vth[NROWS * DIMM];
__device__ __align__(16) __nv_bfloat16 g_Vtl[NROWS * DIMM];
__device__ __align__(16) __nv_bfloat16 g_Ohi[NROWS * DIMM];
__device__ __align__(16) __nv_bfloat16 g_Olo[NROWS * DIMM];
// transposed weights [n][k] (K-major); 4 projection weights + Wo
__device__ __align__(16) __nv_bfloat16 g_Wthi[4 * DIMM * DIMM];
__device__ __align__(16) __nv_bfloat16 g_Wtlo[4 * DIMM * DIMM];
__device__ __align__(16) __nv_bfloat16 g_Wothi[DIMM * DIMM];
__device__ __align__(16) __nv_bfloat16 g_Wotlo[DIMM * DIMM];

// ---------------------------------------------------------------------------
// helpers
// ---------------------------------------------------------------------------
__device__ __forceinline__ uint32_t smem_u32(const void* p) {
    uint32_t a;
    asm("{ .reg .u64 t; cvta.to.shared.u64 t, %1; cvt.u32.u64 %0, t; }" : "=r"(a) : "l"(p));
    return a;
}
__device__ __forceinline__ void cp_async16(uint32_t dst, const void* src) {
    asm volatile("cp.async.cg.shared.global [%0], [%1], 16;" :: "r"(dst), "l"(src));
}
__device__ __forceinline__ void cp_commit() {
    asm volatile("cp.async.commit_group;" ::: "memory");
}
template <int N>
__device__ __forceinline__ void cp_wait() {
    asm volatile("cp.async.wait_group %0;" :: "n"(N) : "memory");
}
__device__ __forceinline__ void mma16816(float* c,
                                         uint32_t a0, uint32_t a1, uint32_t a2, uint32_t a3,
                                         uint32_t b0, uint32_t b1) {
    asm volatile(
        "mma.sync.aligned.m16n8k16.row.col.f32.bf16.bf16.f32 "
        "{%0,%1,%2,%3}, {%4,%5,%6,%7}, {%8,%9}, {%0,%1,%2,%3};"
        : "+f"(c[0]), "+f"(c[1]), "+f"(c[2]), "+f"(c[3])
        : "r"(a0), "r"(a1), "r"(a2), "r"(a3), "r"(b0), "r"(b1));
}
__device__ __forceinline__ void split_bf16(float v, __nv_bfloat16& h, __nv_bfloat16& l) {
    h = __float2bfloat16(v);
    l = __float2bfloat16(v - __bfloat162float(h));
}
__device__ __forceinline__ uint32_t pack2(__nv_bfloat16 a, __nv_bfloat16 b) {
    __nv_bfloat162 t = __halves2bfloat162(a, b);
    return *(uint32_t*)&t;
}
__device__ __forceinline__ uint32_t ld32s(const __nv_bfloat16* p) {
    return *(const uint32_t*)p;
}

// ---------------------------------------------------------------------------
// merged preprocessing: z<5 -> weight transpose+split; z>=5 -> x split
// grid (16,16,9), 256 threads
// ---------------------------------------------------------------------------
__global__ void __launch_bounds__(256) prep_kernel(
    const float* __restrict__ x,
    const float* __restrict__ Wq, const float* __restrict__ Wk,
    const float* __restrict__ Wv, const float* __restrict__ Wg,
    const float* __restrict__ Wo)
{
    if (blockIdx.z < 5) {
        __shared__ float t[32][33];
        const int w = blockIdx.z;
        const float* __restrict__ W = (w == 0) ? Wq : (w == 1) ? Wk : (w == 2) ? Wv : (w == 3) ? Wg : Wo;
        __nv_bfloat16* __restrict__ Hi = (w < 4) ? (g_Wthi + (size_t)w * DIMM * DIMM) : g_Wothi;
        __nv_bfloat16* __restrict__ Lo = (w < 4) ? (g_Wtlo + (size_t)w * DIMM * DIMM) : g_Wotlo;

        const int tx = threadIdx.x & 31, ty = threadIdx.x >> 5;
        const int n0 = blockIdx.x * 32, k0 = blockIdx.y * 32;
#pragma unroll
        for (int j = 0; j < 4; j++)
            t[ty + 8 * j][tx] = W[(size_t)(k0 + ty + 8 * j) * DIMM + n0 + tx];
        __syncthreads();
#pragma unroll
        for (int j = 0; j < 4; j++) {
            float v = t[tx][ty + 8 * j];
            __nv_bfloat16 h, l; split_bf16(v, h, l);
            size_t o = (size_t)(n0 + ty + 8 * j) * DIMM + k0 + tx;
            Hi[o] = h; Lo[o] = l;
        }
    } else {
        int bid = (blockIdx.z - 5) * 256 + blockIdx.y * 16 + blockIdx.x;  // 0..1023
        int i4 = (bid * 256 + threadIdx.x) * 4;
        float4 v = *(const float4*)(x + i4);
        __nv_bfloat16 h0, h1, h2, h3, l0, l1, l2, l3;
        split_bf16(v.x, h0, l0); split_bf16(v.y, h1, l1);
        split_bf16(v.z, h2, l2); split_bf16(v.w, h3, l3);
        *(__nv_bfloat162*)(g_Xhi + i4)     = __halves2bfloat162(h0, h1);
        *(__nv_bfloat162*)(g_Xhi + i4 + 2) = __halves2bfloat162(h2, h3);
        *(__nv_bfloat162*)(g_Xlo + i4)     = __halves2bfloat162(l0, l1);
        *(__nv_bfloat162*)(g_Xlo + i4 + 2) = __halves2bfloat162(l2, l3);
    }
}

// ---------------------------------------------------------------------------
// split-bf16 HMMA GEMM core
// mode: 0 plain float out, 1 relu->bf16 hi/lo, 2 split->transposed Vt, 3 sigmoid->float
// ---------------------------------------------------------------------------
#define PADK 40
#define BUF_ELEMS (128 * PADK)
#define STAGE_ELEMS (4 * BUF_ELEMS)
#define GEMM_SMEM_BYTES (2 * STAGE_ELEMS * 2)  // 81920

__device__ __forceinline__ void mma_gemm_tile(
    const __nv_bfloat16* __restrict__ Ahi, const __nv_bfloat16* __restrict__ Alo,
    const __nv_bfloat16* __restrict__ Bhi, const __nv_bfloat16* __restrict__ Blo,
    int mode, int m0, int n0,
    float* __restrict__ fout, __nv_bfloat16* __restrict__ ohi,
    __nv_bfloat16* __restrict__ olo, const float* __restrict__ bias)
{
    extern __shared__ __nv_bfloat16 sm[];
    const uint32_t smb = smem_u32(sm);

    const int tid = threadIdx.x;
    const int wid = tid >> 5;
    const int lane = tid & 31;
    const int wm = wid >> 2;
    const int wn = wid & 3;
    const int gid = lane >> 2;
    const int qid = lane & 3;

    float c[4][4][4];
#pragma unroll
    for (int i = 0; i < 4; i++)
#pragma unroll
        for (int j = 0; j < 4; j++)
#pragma unroll
            for (int k = 0; k < 4; k++) c[i][j][k] = 0.f;

    auto prefetch = [&](int chunk, int stage) {
        const int k0 = chunk * 32;
#pragma unroll
        for (int t = 0; t < 2; t++) {
            int id = tid + t * 256;
            int row = id >> 2, seg = id & 3;
            uint32_t soff = (uint32_t)(row * PADK + seg * 8) * 2;
            uint32_t sb = smb + (uint32_t)stage * (STAGE_ELEMS * 2) + soff;
            size_t ao = (size_t)(m0 + row) * DIMM + k0 + seg * 8;
            size_t bo = (size_t)(n0 + row) * DIMM + k0 + seg * 8;
            cp_async16(sb + 0 * (BUF_ELEMS * 2), Ahi + ao);
            cp_async16(sb + 1 * (BUF_ELEMS * 2), Alo + ao);
            cp_async16(sb + 2 * (BUF_ELEMS * 2), Bhi + bo);
            cp_async16(sb + 3 * (BUF_ELEMS * 2), Blo + bo);
        }
        cp_commit();
    };

    prefetch(0, 0);

    for (int chunk = 0; chunk < 16; chunk++) {
        const int stage = chunk & 1;
        if (chunk + 1 < 16) {
            prefetch(chunk + 1, stage ^ 1);
            cp_wait<1>();
        } else {
            cp_wait<0>();
        }
        __syncthreads();

        const __nv_bfloat16* sA_hi = sm + stage * STAGE_ELEMS;
        const __nv_bfloat16* sA_lo = sA_hi + BUF_ELEMS;
        const __nv_bfloat16* sB_hi = sA_hi + 2 * BUF_ELEMS;
        const __nv_bfloat16* sB_lo = sA_hi + 3 * BUF_ELEMS;

#pragma unroll
        for (int ks = 0; ks < 2; ks++) {
            const int kq = ks * 16 + qid * 2;
            uint32_t ahi[4][4], alo[4][4];
#pragma unroll
            for (int mf = 0; mf < 4; mf++) {
                int r = wm * 64 + mf * 16 + gid;
                const __nv_bfloat16* ph = sA_hi + r * PADK + kq;
                const __nv_bfloat16* pl = sA_lo + r * PADK + kq;
                ahi[mf][0] = ld32s(ph);
                ahi[mf][1] = ld32s(ph + 8 * PADK);
                ahi[mf][2] = ld32s(ph + 8);
                ahi[mf][3] = ld32s(ph + 8 * PADK + 8);
                alo[mf][0] = ld32s(pl);
                alo[mf][1] = ld32s(pl + 8 * PADK);
                alo[mf][2] = ld32s(pl + 8);
                alo[mf][3] = ld32s(pl + 8 * PADK + 8);
            }
#pragma unroll
            for (int nf = 0; nf < 4; nf++) {
                int n = wn * 32 + nf * 8 + gid;
                const __nv_bfloat16* pbh = sB_hi + n * PADK + kq;
                const __nv_bfloat16* pbl = sB_lo + n * PADK + kq;
                uint32_t bh0 = ld32s(pbh);
                uint32_t bh1 = ld32s(pbh + 8);
                uint32_t bl0 = ld32s(pbl);
                uint32_t bl1 = ld32s(pbl + 8);
#pragma unroll
                for (int mf = 0; mf < 4; mf++) {
                    mma16816(c[mf][nf], ahi[mf][0], ahi[mf][1], ahi[mf][2], ahi[mf][3], bh0, bh1);
                    mma16816(c[mf][nf], ahi[mf][0], ahi[mf][1], ahi[mf][2], ahi[mf][3], bl0, bl1);
                    mma16816(c[mf][nf], alo[mf][0], alo[mf][1], alo[mf][2], alo[mf][3], bh0, bh1);
                }
            }
        }
        __syncthreads();
    }

#pragma unroll
    for (int mf = 0; mf < 4; mf++) {
#pragma unroll
        for (int nf = 0; nf < 4; nf++) {
            int m = m0 + wm * 64 + mf * 16 + gid;
            int n = n0 + wn * 32 + nf * 8 + qid * 2;
            float v0 = c[mf][nf][0], v1 = c[mf][nf][1];
            float v2 = c[mf][nf][2], v3 = c[mf][nf][3];
            if (mode == 0) {
                *(float2*)(fout + (size_t)m * DIMM + n)       = make_float2(v0, v1);
                *(float2*)(fout + (size_t)(m + 8) * DIMM + n) = make_float2(v2, v3);
            } else if (mode == 1) {
                v0 = fmaxf(v0, 0.f); v1 = fmaxf(v1, 0.f);
                v2 = fmaxf(v2, 0.f); v3 = fmaxf(v3, 0.f);
                __nv_bfloat16 h0, h1, h2, h3, l0, l1, l2, l3;
                split_bf16(v0, h0, l0); split_bf16(v1, h1, l1);
                split_bf16(v2, h2, l2); split_bf16(v3, h3, l3);
                *(__nv_bfloat162*)(ohi + (size_t)m * DIMM + n)       = __halves2bfloat162(h0, h1);
                *(__nv_bfloat162*)(ohi + (size_t)(m + 8) * DIMM + n) = __halves2bfloat162(h2, h3);
                *(__nv_bfloat162*)(olo + (size_t)m * DIMM + n)       = __halves2bfloat162(l0, l1);
                *(__nv_bfloat162*)(olo + (size_t)(m + 8) * DIMM + n) = __halves2bfloat162(l2, l3);
            } else if (mode == 2) {
                int bb = m >> 10, tt = m & 1023;
                int hh = n >> 6, dd = n & 63;
                size_t base = ((size_t)((bb * 8 + hh) * 64 + dd)) * 1024 + tt;
                __nv_bfloat16 h0, h1, h2, h3, l0, l1, l2, l3;
                split_bf16(v0, h0, l0); split_bf16(v1, h1, l1);
                split_bf16(v2, h2, l2); split_bf16(v3, h3, l3);
                ohi[base] = h0;        olo[base] = l0;
                ohi[base + 1024] = h1; olo[base + 1024] = l1;
                ohi[base + 8] = h2;    olo[base + 8] = l2;
                ohi[base + 1032] = h3; olo[base + 1032] = l3;
            } else {
                float b0 = bias[n], b1 = bias[n + 1];
                v0 = 1.f / (1.f + expf(-(v0 + b0)));
                v1 = 1.f / (1.f + expf(-(v1 + b1)));
                v2 = 1.f / (1.f + expf(-(v2 + b0)));
                v3 = 1.f / (1.f + expf(-(v3 + b1)));
                *(float2*)(fout + (size_t)m * DIMM + n)       = make_float2(v0, v1);
                *(float2*)(fout + (size_t)(m + 8) * DIMM + n) = make_float2(v2, v3);
            }
        }
    }
}

__global__ void __launch_bounds__(256) mma_proj_kernel(const float* __restrict__ bg)
{
    const int zi = blockIdx.z;
    const __nv_bfloat16* Bh = g_Wthi + (size_t)zi * DIMM * DIMM;
    const __nv_bfloat16* Bl = g_Wtlo + (size_t)zi * DIMM * DIMM;
    const int m0 = blockIdx.y * 128, n0 = blockIdx.x * 128;
    if (zi == 0)
        mma_gemm_tile(g_Xhi, g_Xlo, Bh, Bl, 1, m0, n0, nullptr, g_Qh, g_Ql, nullptr);
    else if (zi == 1)
        mma_gemm_tile(g_Xhi, g_Xlo, Bh, Bl, 1, m0, n0, nullptr, g_Kh, g_Kl, nullptr);
    else if (zi == 2)
        mma_gemm_tile(g_Xhi, g_Xlo, Bh, Bl, 2, m0, n0, nullptr, g_Vth, g_Vtl, nullptr);
    else
        mma_gemm_tile(g_Xhi, g_Xlo, Bh, Bl, 3, m0, n0, g_G, nullptr, nullptr, bg);
}

__global__ void __launch_bounds__(256) mma_out_kernel(float* __restrict__ out)
{
    mma_gemm_tile(g_Ohi, g_Olo, g_Wothi, g_Wotlo, 0, blockIdx.y * 128, blockIdx.x * 128,
                  out, nullptr, nullptr, nullptr);
}

// ---------------------------------------------------------------------------
// HMMA cosformer attention, split-K over key range (2 segments per qtile)
// grid (32, 8, 2): blockIdx.x = qtile*2 + seg (reversed for longest-first)
// ---------------------------------------------------------------------------
#define APAD 72
#define ATILE (64 * APAD)
#define AQH 0
#define AQL (ATILE)
#define AKH (2 * ATILE)
#define AKL (4 * ATILE)
#define AVH (6 * ATILE)
#define AVL (8 * ATILE)
#define ATRIG_C (10 * ATILE * 2)
#define ATTN2_SMEM_BYTES (10 * ATILE * 2 + 2 * 2 * 64 * 4)

__global__ void __launch_bounds__(128) attn3_kernel()
{
    extern __shared__ __nv_bfloat16 asm_[];
    const uint32_t smb = smem_u32(asm_);
    float* cks = (float*)((char*)asm_ + ATRIG_C);
    float* sks = cks + 128;

    const int i = 15 - (blockIdx.x >> 1);
    const int seg = blockIdx.x & 1;
    const int h = blockIdx.y;
    const int b = blockIdx.z;
    const int tid = threadIdx.x;
    const int wid = tid >> 5;
    const int lane = tid & 31;
    const int gid = lane >> 2;
    const int qid = lane & 3;

    const int nj = i + 1;
    const int h0 = (nj + 1) >> 1;
    const int jlo = seg ? h0 : 0;
    const int jhi = seg ? nj : h0;

    const int qrow0 = b * TSEQ + i * 64;
    const float ANG = (float)(3.14159265358979323846 / 2048.0);

    // prologue: load Q tile (hi/lo) + first K/V stage
    {
#pragma unroll
        for (int t = 0; t < 4; t++) {
            int id = tid + t * 128;
            int row = id >> 3, sgm = id & 7;
            size_t src = (size_t)(qrow0 + row) * DIMM + h * DKH + sgm * 8;
            uint32_t so = (uint32_t)(row * APAD + sgm * 8) * 2;
            cp_async16(smb + AQH * 2 + so, g_Qh + src);
            cp_async16(smb + AQL * 2 + so, g_Ql + src);
        }
    }
    auto prefetch_kv = [&](int j, int s) {
#pragma unroll
        for (int t = 0; t < 4; t++) {
            int id = tid + t * 128;
            int row = id >> 3, sgm = id & 7;
            uint32_t so = (uint32_t)(row * APAD + sgm * 8) * 2 + (uint32_t)s * (ATILE * 2);
            size_t ksrc = (size_t)(b * TSEQ + j * 64 + row) * DIMM + h * DKH + sgm * 8;
            cp_async16(smb + AKH * 2 + so, g_Kh + ksrc);
            cp_async16(smb + AKL * 2 + so, g_Kl + ksrc);
            size_t vsrc = (size_t)((b * 8 + h) * 64 + row) * TSEQ + j * 64 + sgm * 8;
            cp_async16(smb + AVH * 2 + so, g_Vth + vsrc);
            cp_async16(smb + AVL * 2 + so, g_Vtl + vsrc);
        }
    };
    if (jlo < jhi) prefetch_kv(jlo, 0);
    cp_commit();

    float cq0, sq0, cq1, sq1;
    {
        float a0 = (float)(i * 64 + wid * 16 + gid) * ANG;
        float a1 = (float)(i * 64 + wid * 16 + gid + 8) * ANG;
        sincosf(a0, &sq0, &cq0);
        sincosf(a1, &sq1, &cq1);
    }

    float oacc[8][4];
#pragma unroll
    for (int nf = 0; nf < 8; nf++)
#pragma unroll
        for (int k = 0; k < 4; k++) oacc[nf][k] = 0.f;
    float z0 = 0.f, z1 = 0.f;

    const __nv_bfloat16* Qhs = asm_ + AQH;
    const __nv_bfloat16* Qls = asm_ + AQL;

    for (int j = jlo; j < jhi; j++) {
        const int s = (j - jlo) & 1;
        cp_wait<0>();
        __syncthreads();
        if (j + 1 < jhi) { prefetch_kv(j + 1, s ^ 1); cp_commit(); }
        if (tid < 64) {
            float ss, cc;
            sincosf((float)(j * 64 + tid) * ANG, &ss, &cc);
            cks[s * 64 + tid] = cc;
            sks[s * 64 + tid] = ss;
        }
        __syncthreads();

        const __nv_bfloat16* Khs = asm_ + AKH + s * ATILE;
        const __nv_bfloat16* Kls = asm_ + AKL + s * ATILE;
        const __nv_bfloat16* Vhs = asm_ + AVH + s * ATILE;
        const __nv_bfloat16* Vls = asm_ + AVL + s * ATILE;

        // --- S = Q K^T ---
        float sc[8][4];
#pragma unroll
        for (int nf = 0; nf < 8; nf++)
#pragma unroll
            for (int k = 0; k < 4; k++) sc[nf][k] = 0.f;

#pragma unroll
        for (int ks = 0; ks < 4; ks++) {
            const int kq = ks * 16 + qid * 2;
            const __nv_bfloat16* ph = Qhs + (wid * 16 + gid) * APAD + kq;
            const __nv_bfloat16* pl = Qls + (wid * 16 + gid) * APAD + kq;
            uint32_t qh0 = ld32s(ph), qh1 = ld32s(ph + 8 * APAD);
            uint32_t qh2 = ld32s(ph + 8), qh3 = ld32s(ph + 8 * APAD + 8);
            uint32_t ql0 = ld32s(pl), ql1 = ld32s(pl + 8 * APAD);
            uint32_t ql2 = ld32s(pl + 8), ql3 = ld32s(pl + 8 * APAD + 8);
#pragma unroll
            for (int nf = 0; nf < 8; nf++) {
                const __nv_bfloat16* pk = Khs + (nf * 8 + gid) * APAD + kq;
                const __nv_bfloat16* pkl = Kls + (nf * 8 + gid) * APAD + kq;
                uint32_t kh0 = ld32s(pk), kh1 = ld32s(pk + 8);
                uint32_t kl0 = ld32s(pkl), kl1 = ld32s(pkl + 8);
                mma16816(sc[nf], qh0, qh1, qh2, qh3, kh0, kh1);
                mma16816(sc[nf], qh0, qh1, qh2, qh3, kl0, kl1);
                mma16816(sc[nf], ql0, ql1, ql2, ql3, kh0, kh1);
            }
        }

        // --- weight, mask, z, split to A-frags ---
        uint32_t ah[4][4], al[4][4];
        const bool diag = (j == i);
        const int lr0 = wid * 16 + gid, lr1 = lr0 + 8;
#pragma unroll
        for (int nf = 0; nf < 8; nf++) {
            const int c0 = nf * 8 + qid * 2, c1 = c0 + 1;
            float ck0 = cks[s * 64 + c0], sk0 = sks[s * 64 + c0];
            float ck1 = cks[s * 64 + c1], sk1 = sks[s * 64 + c1];
            float v0 = sc[nf][0] * (cq0 * ck0 + sq0 * sk0);
            float v1 = sc[nf][1] * (cq0 * ck1 + sq0 * sk1);
            float v2 = sc[nf][2] * (cq1 * ck0 + sq1 * sk0);
            float v3 = sc[nf][3] * (cq1 * ck1 + sq1 * sk1);
            if (diag) {
                if (c0 > lr0) v0 = 0.f;
                if (c1 > lr0) v1 = 0.f;
                if (c0 > lr1) v2 = 0.f;
                if (c1 > lr1) v3 = 0.f;
            }
            z0 += v0 + v1;
            z1 += v2 + v3;
            __nv_bfloat16 h0, h1, h2, h3, l0, l1, l2, l3;
            split_bf16(v0, h0, l0); split_bf16(v1, h1, l1);
            split_bf16(v2, h2, l2); split_bf16(v3, h3, l3);
            const int f = nf >> 1;
            if ((nf & 1) == 0) {
                ah[f][0] = pack2(h0, h1); ah[f][1] = pack2(h2, h3);
                al[f][0] = pack2(l0, l1); al[f][1] = pack2(l2, l3);
            } else {
                ah[f][2] = pack2(h0, h1); ah[f][3] = pack2(h2, h3);
                al[f][2] = pack2(l0, l1); al[f][3] = pack2(l2, l3);
            }
        }

        // --- O += S Vt^T ---
#pragma unroll
        for (int f = 0; f < 4; f++) {
            const int kq = f * 16 + qid * 2;
#pragma unroll
            for (int nf = 0; nf < 8; nf++) {
                const __nv_bfloat16* pv = Vhs + (nf * 8 + gid) * APAD + kq;
                const __nv_bfloat16* pvl = Vls + (nf * 8 + gid) * APAD + kq;
                uint32_t vh0 = ld32s(pv), vh1 = ld32s(pv + 8);
                uint32_t vl0 = ld32s(pvl), vl1 = ld32s(pvl + 8);
                mma16816(oacc[nf], ah[f][0], ah[f][1], ah[f][2], ah[f][3], vh0, vh1);
                mma16816(oacc[nf], al[f][0], al[f][1], al[f][2], al[f][3], vh0, vh1);
                mma16816(oacc[nf], ah[f][0], ah[f][1], ah[f][2], ah[f][3], vl0, vl1);
            }
        }
    }

    // z reduce over quad
    z0 += __shfl_xor_sync(0xffffffffu, z0, 1);
    z0 += __shfl_xor_sync(0xffffffffu, z0, 2);
    z1 += __shfl_xor_sync(0xffffffffu, z1, 1);
    z1 += __shfl_xor_sync(0xffffffffu, z1, 2);

    const int gr0 = qrow0 + wid * 16 + gid;
    const int gr1 = gr0 + 8;

    float* Op = seg ? g_Opart1 : g_Opart0;
    float* zp = seg ? g_zpart1 : g_zpart0;
    if (qid == 0) {
        zp[(size_t)gr0 * NHEAD + h] = z0;
        zp[(size_t)gr1 * NHEAD + h] = z1;
    }
#pragma unroll
    for (int nf = 0; nf < 8; nf++) {
        const int col = h * DKH + nf * 8 + qid * 2;
        *(float2*)(Op + (size_t)gr0 * DIMM + col) = make_float2(oacc[nf][0], oacc[nf][1]);
        *(float2*)(Op + (size_t)gr1 * DIMM + col) = make_float2(oacc[nf][2], oacc[nf][3]);
    }
}

// ---------------------------------------------------------------------------
// combine: O = (P0+P1)/max(z0+z1,1e-6) * gate -> bf16 hi/lo
// ---------------------------------------------------------------------------
__global__ void __launch_bounds__(256) combine_kernel()
{
    int i4 = (blockIdx.x * 256 + threadIdx.x) * 4;
    int row = i4 >> 9;
    int col = i4 & 511;
    int h = col >> 6;
    float z = g_zpart0[(size_t)row * NHEAD + h] + g_zpart1[(size_t)row * NHEAD + h];
    float zi = 1.f / fmaxf(z, 1e-6f);
    float4 a = *(const float4*)(g_Opart0 + i4);
    float4 bp = *(const float4*)(g_Opart1 + i4);
    float4 g = *(const float4*)(g_G + i4);
    float v0 = (a.x + bp.x) * zi * g.x;
    float v1 = (a.y + bp.y) * zi * g.y;
    float v2 = (a.z + bp.z) * zi * g.z;
    float v3 = (a.w + bp.w) * zi * g.w;
    __nv_bfloat16 h0, h1, h2, h3, l0, l1, l2, l3;
    split_bf16(v0, h0, l0); split_bf16(v1, h1, l1);
    split_bf16(v2, h2, l2); split_bf16(v3, h3, l3);
    *(__nv_bfloat162*)(g_Ohi + i4)     = __halves2bfloat162(h0, h1);
    *(__nv_bfloat162*)(g_Ohi + i4 + 2) = __halves2bfloat162(h2, h3);
    *(__nv_bfloat162*)(g_Olo + i4)     = __halves2bfloat162(l0, l1);
    *(__nv_bfloat162*)(g_Olo + i4 + 2) = __halves2bfloat162(l2, l3);
}

// ---------------------------------------------------------------------------
extern "C" void kernel_launch(void* const* d_in, const int* in_sizes, int n_in,
                              void* d_out, int out_size)
{
    const float* x  = (const float*)d_in[0];
    const float* Wq = (const float*)d_in[1];
    const float* Wk = (const float*)d_in[2];
    const float* Wv = (const float*)d_in[3];
    const float* Wo = (const float*)d_in[4];
    const float* Wg = (const float*)d_in[5];
    const float* bg = (const float*)d_in[6];

    cudaFuncSetAttribute(mma_proj_kernel, cudaFuncAttributeMaxDynamicSharedMemorySize, GEMM_SMEM_BYTES);
    cudaFuncSetAttribute(mma_out_kernel, cudaFuncAttributeMaxDynamicSharedMemorySize, GEMM_SMEM_BYTES);
    cudaFuncSetAttribute(attn3_kernel, cudaFuncAttributeMaxDynamicSharedMemorySize, ATTN2_SMEM_BYTES);

    prep_kernel<<<dim3(16, 16, 9), 256>>>(x, Wq, Wk, Wv, Wg, Wo);
    mma_proj_kernel<<<dim3(4, 16, 4), 256, GEMM_SMEM_BYTES>>>(bg);
    attn3_kernel<<<dim3(32, 8, 2), 128, ATTN2_SMEM_BYTES>>>();
    combine_kernel<<<NROWS * DIMM / 1024, 256>>>();
    mma_out_kernel<<<dim3(4, 16), 256, GEMM_SMEM_BYTES>>>((float*)d_out);
}